// round 1
// baseline (speedup 1.0000x reference)
#include <cuda_runtime.h>
#include <math.h>

#define N_NODES 200000
#define N_EDGES 12800000
#define ALPHA   0.1f
#define DT      0.01f
#define EPS_    1e-9f
#define DIFF_   10.0f
#define HARD    1.57079632679489662f

// Scratch (device globals — no allocation allowed)
__device__ float2 g_uv[N_NODES];    // per-node pre-rotated (u,v) = e^{-i phi}(x+iy)
__device__ int    g_row[N_NODES];   // CSR row start via lower_bound on sorted edge_src

// ---------------------------------------------------------------------------
// K1: per-node prep. Compute uv[i] and row_start[i] = lower_bound(edge_src, i).
// Adjacent threads' binary searches share almost the whole path -> cache friendly.
// ---------------------------------------------------------------------------
__global__ void __launch_bounds__(256) prep_kernel(
    const float* __restrict__ phase,
    const float* __restrict__ xy,
    const int*   __restrict__ src)
{
    int i = blockIdx.x * blockDim.x + threadIdx.x;
    if (i >= N_NODES) return;

    float s, c;
    __sincosf(phase[i], &s, &c);               // phase in ±2pi: fast path fine
    float x = xy[2 * i], y = xy[2 * i + 1];
    g_uv[i] = make_float2(fmaf(c, x, s * y), fmaf(c, y, -s * x));

    // lower_bound(src, src+N_EDGES, i)
    int lo = 0, hi = N_EDGES;
    while (lo < hi) {
        int mid = (lo + hi) >> 1;
        if (__ldg(&src[mid]) < i) lo = mid + 1; else hi = mid;
    }
    g_row[i] = lo;
}

// ---------------------------------------------------------------------------
// K2: one warp per node. Sum uv over the node's edge range (coalesced dst
// reads, L2-resident uv gathers), shfl-reduce, then lane 0 rotates by
// e^{i phi_src} and does the full pointwise finalize + output writes.
// ---------------------------------------------------------------------------
__global__ void __launch_bounds__(256) edge_finalize_kernel(
    const float* __restrict__ phase,
    const float* __restrict__ xy,
    const float* __restrict__ xy_dot_old,
    const float* __restrict__ w,
    const float* __restrict__ amp,
    const float* __restrict__ ha,
    const int*   __restrict__ dst,
    float*       __restrict__ out)
{
    int gtid = blockIdx.x * blockDim.x + threadIdx.x;
    int node = gtid >> 5;
    if (node >= N_NODES) return;
    int lane = gtid & 31;

    int beg = g_row[node];
    int end = (node == N_NODES - 1) ? N_EDGES : g_row[node + 1];

    float U = 0.0f, V = 0.0f;
    for (int j = beg + lane; j < end; j += 32) {
        int d = __ldg(&dst[j]);
        float2 uv = g_uv[d];
        U += uv.x;
        V += uv.y;
    }
    #pragma unroll
    for (int o = 16; o > 0; o >>= 1) {
        U += __shfl_down_sync(0xffffffffu, U, o);
        V += __shfl_down_sync(0xffffffffu, V, o);
    }

    if (lane == 0) {
        float s, c;
        __sincosf(phase[node], &s, &c);
        float sum_x = fmaf(c, U, -s * V);
        float sum_y = fmaf(s, U,  c * V);

        float x  = xy[2 * node],         y  = xy[2 * node + 1];
        float xd = xy_dot_old[2 * node], yd = xy_dot_old[2 * node + 1];

        float r2   = fmaf(x, x, y * y);
        float a    = ALPHA * (1.0f - r2 * r2);
        float zeta = 1.0f - ha[node] * ((xd + EPS_) / (fabsf(xd) + EPS_));
        float b    = w[node] / (zeta + EPS_);

        float kx = fmaf(a, x, -b * y);
        float ky = fmaf(b, x,  a * y);

        float x_dot = fminf(fmaxf(kx + sum_x, xd - DIFF_), xd + DIFF_);
        float y_dot = fminf(fmaxf(ky + sum_y, yd - DIFF_), yd + DIFF_);

        float xn = fmaf(x_dot, DT, x);
        float yn = fmaf(y_dot, DT, y);
        float ang = fminf(fmaxf(amp[node] * yn, -HARD), HARD);

        out[node] = ang;                                  // angles
        out[N_NODES + 2 * node]     = xn;                 // xy_new
        out[N_NODES + 2 * node + 1] = yn;
        out[3 * N_NODES + 2 * node]     = x;              // xy_dot_old_new = xy
        out[3 * N_NODES + 2 * node + 1] = y;
    }
}

extern "C" void kernel_launch(void* const* d_in, const int* in_sizes, int n_in,
                              void* d_out, int out_size)
{
    const float* xy         = (const float*)d_in[0];
    const float* xy_dot_old = (const float*)d_in[1];
    const float* phase      = (const float*)d_in[2];
    const float* w          = (const float*)d_in[3];
    const float* amplitudes = (const float*)d_in[4];
    const float* ha         = (const float*)d_in[5];
    const int*   edge_src   = (const int*)d_in[6];
    const int*   edge_dst   = (const int*)d_in[7];
    float* out = (float*)d_out;

    int blocks1 = (N_NODES + 255) / 256;
    prep_kernel<<<blocks1, 256>>>(phase, xy, edge_src);

    int blocks2 = (N_NODES * 32 + 255) / 256;
    edge_finalize_kernel<<<blocks2, 256>>>(phase, xy, xy_dot_old, w, amplitudes,
                                           ha, edge_dst, out);
}

// round 2
// speedup vs baseline: 1.1930x; 1.1930x over previous
#include <cuda_runtime.h>
#include <cuda_fp16.h>
#include <math.h>

#define N_NODES 200000
#define N_EDGES 12800000
#define ALPHA   0.1f
#define DT      0.01f
#define EPS_    1e-9f
#define DIFF_   10.0f
#define HARD    1.57079632679489662f

// Scratch (device globals — no allocation allowed)
__device__ __half2 g_uv[N_NODES];      // pre-rotated (u,v) = e^{-i phi}(x+iy), half2 for L1 density
__device__ int     g_row[N_NODES + 1]; // CSR row starts via lower_bound on sorted edge_src
__device__ float2  g_sum[N_NODES];     // per-node gathered sum (pre-rotation)

// ---------------------------------------------------------------------------
// K1: per-node prep. uv[i] and row_start[i] = lower_bound(edge_src, i).
// ---------------------------------------------------------------------------
__global__ void __launch_bounds__(256) prep_kernel(
    const float* __restrict__ phase,
    const float* __restrict__ xy,
    const int*   __restrict__ src)
{
    int i = blockIdx.x * blockDim.x + threadIdx.x;
    if (i >= N_NODES) return;
    if (i == 0) g_row[N_NODES] = N_EDGES;

    float s, c;
    __sincosf(phase[i], &s, &c);
    float2 p = ((const float2*)xy)[i];
    float u = fmaf(c, p.x,  s * p.y);
    float v = fmaf(c, p.y, -s * p.x);
    g_uv[i] = __floats2half2_rn(u, v);

    // lower_bound(src, src+N_EDGES, i) — adjacent threads share the search path
    int lo = 0, hi = N_EDGES;
    while (lo < hi) {
        int mid = (lo + hi) >> 1;
        if (__ldg(&src[mid]) < i) lo = mid + 1; else hi = mid;
    }
    g_row[i] = lo;
}

// ---------------------------------------------------------------------------
// K2: one warp per node. Pure gather+reduce; no per-node finalize tail.
// dst stream read with evict-first (.cs) so it doesn't thrash uv out of L1.
// ---------------------------------------------------------------------------
__global__ void __launch_bounds__(256) edge_kernel(
    const int* __restrict__ dst)
{
    int gtid = blockIdx.x * blockDim.x + threadIdx.x;
    int node = gtid >> 5;
    if (node >= N_NODES) return;
    int lane = gtid & 31;

    int beg = g_row[node];
    int end = g_row[node + 1];

    float U = 0.0f, V = 0.0f;
    int j = beg + lane;
    // 2-deep unroll: two independent gathers in flight per lane
    for (; j + 32 < end; j += 64) {
        int d0 = __ldcs(&dst[j]);
        int d1 = __ldcs(&dst[j + 32]);
        float2 f0 = __half22float2(__ldg(&g_uv[d0]));
        float2 f1 = __half22float2(__ldg(&g_uv[d1]));
        U += f0.x + f1.x;
        V += f0.y + f1.y;
    }
    for (; j < end; j += 32) {
        int d = __ldcs(&dst[j]);
        float2 f = __half22float2(__ldg(&g_uv[d]));
        U += f.x;
        V += f.y;
    }

    #pragma unroll
    for (int o = 16; o > 0; o >>= 1) {
        U += __shfl_down_sync(0xffffffffu, U, o);
        V += __shfl_down_sync(0xffffffffu, V, o);
    }
    if (lane == 0) g_sum[node] = make_float2(U, V);
}

// ---------------------------------------------------------------------------
// K3: thread-per-node finalize. Fully coalesced loads/stores, vectorized.
// ---------------------------------------------------------------------------
__global__ void __launch_bounds__(256) finalize_kernel(
    const float* __restrict__ phase,
    const float* __restrict__ xy,
    const float* __restrict__ xy_dot_old,
    const float* __restrict__ w,
    const float* __restrict__ amp,
    const float* __restrict__ ha,
    float*       __restrict__ out)
{
    int i = blockIdx.x * blockDim.x + threadIdx.x;
    if (i >= N_NODES) return;

    float2 sv = g_sum[i];
    float s, c;
    __sincosf(phase[i], &s, &c);
    float sum_x = fmaf(c, sv.x, -s * sv.y);
    float sum_y = fmaf(s, sv.x,  c * sv.y);

    float2 p  = ((const float2*)xy)[i];
    float2 pd = ((const float2*)xy_dot_old)[i];

    float r2   = fmaf(p.x, p.x, p.y * p.y);
    float a    = ALPHA * (1.0f - r2 * r2);
    float zeta = 1.0f - ha[i] * ((pd.x + EPS_) / (fabsf(pd.x) + EPS_));
    float b    = w[i] / (zeta + EPS_);

    float kx = fmaf(a, p.x, -b * p.y);
    float ky = fmaf(b, p.x,  a * p.y);

    float x_dot = fminf(fmaxf(kx + sum_x, pd.x - DIFF_), pd.x + DIFF_);
    float y_dot = fminf(fmaxf(ky + sum_y, pd.y - DIFF_), pd.y + DIFF_);

    float xn = fmaf(x_dot, DT, p.x);
    float yn = fmaf(y_dot, DT, p.y);
    float ang = fminf(fmaxf(amp[i] * yn, -HARD), HARD);

    out[i] = ang;                                        // angles
    ((float2*)(out + N_NODES))[i]     = make_float2(xn, yn);   // xy_new
    ((float2*)(out + 3 * N_NODES))[i] = p;                     // xy_dot_old_new = xy
}

extern "C" void kernel_launch(void* const* d_in, const int* in_sizes, int n_in,
                              void* d_out, int out_size)
{
    const float* xy         = (const float*)d_in[0];
    const float* xy_dot_old = (const float*)d_in[1];
    const float* phase      = (const float*)d_in[2];
    const float* w          = (const float*)d_in[3];
    const float* amplitudes = (const float*)d_in[4];
    const float* ha         = (const float*)d_in[5];
    const int*   edge_src   = (const int*)d_in[6];
    const int*   edge_dst   = (const int*)d_in[7];
    float* out = (float*)d_out;

    int blocks1 = (N_NODES + 255) / 256;
    prep_kernel<<<blocks1, 256>>>(phase, xy, edge_src);

    int blocks2 = (N_NODES * 32 + 255) / 256;
    edge_kernel<<<blocks2, 256>>>(edge_dst);

    finalize_kernel<<<blocks1, 256>>>(phase, xy, xy_dot_old, w, amplitudes,
                                      ha, out);
}

// round 3
// speedup vs baseline: 1.1966x; 1.0030x over previous
#include <cuda_runtime.h>
#include <cuda_fp16.h>
#include <math.h>

#define N_NODES 200000
#define N_EDGES 12800000
#define ALPHA   0.1f
#define DT      0.01f
#define EPS_    1e-9f
#define DIFF_   10.0f
#define HARD    1.57079632679489662f

// Scratch (device globals — no allocation allowed)
__device__ __half2 g_uv[N_NODES];   // pre-rotated (u,v) = e^{-i phi}(x+iy)
__device__ float2  g_sum[N_NODES];  // per-node gathered sum (pre-rotation), atomic-accumulated

// ---------------------------------------------------------------------------
// K1: per-node prep. uv[i] = e^{-i phi_i}(x_i + i y_i) as half2; zero g_sum.
// ---------------------------------------------------------------------------
__global__ void __launch_bounds__(256) uv_kernel(
    const float* __restrict__ phase,
    const float* __restrict__ xy)
{
    int i = blockIdx.x * blockDim.x + threadIdx.x;
    if (i >= N_NODES) return;

    float s, c;
    __sincosf(phase[i], &s, &c);
    float2 p = ((const float2*)xy)[i];
    g_uv[i]  = __floats2half2_rn(fmaf(c, p.x, s * p.y), fmaf(c, p.y, -s * p.x));
    g_sum[i] = make_float2(0.0f, 0.0f);
}

// ---------------------------------------------------------------------------
// K2: edge-centric segmented reduction. One thread per edge. edge_src is
// sorted, so within a warp equal keys are contiguous: shfl-up segmented
// inclusive scan, then the last lane of each run atomically adds the run
// partial to g_sum[key]. Runs spanning warps merge via the atomics.
// N_EDGES is a multiple of 32 -> all warps full.
// ---------------------------------------------------------------------------
__global__ void __launch_bounds__(256) edge_scan_kernel(
    const int* __restrict__ src,
    const int* __restrict__ dst)
{
    int j = blockIdx.x * blockDim.x + threadIdx.x;
    if (j >= N_EDGES) return;
    int lane = threadIdx.x & 31;

    int key = __ldcs(&src[j]);
    int d   = __ldcs(&dst[j]);
    float2 f = __half22float2(__ldg(&g_uv[d]));
    float U = f.x, V = f.y;

    // segmented inclusive scan over the warp (keys sorted => eq == same run)
    #pragma unroll
    for (int o = 1; o < 32; o <<= 1) {
        int   uk = __shfl_up_sync(0xffffffffu, key, o);
        float uU = __shfl_up_sync(0xffffffffu, U, o);
        float uV = __shfl_up_sync(0xffffffffu, V, o);
        if (lane >= o && uk == key) { U += uU; V += uV; }
    }

    int nk = __shfl_down_sync(0xffffffffu, key, 1);
    if (lane == 31 || nk != key) {
        atomicAdd(&g_sum[key].x, U);
        atomicAdd(&g_sum[key].y, V);
    }
}

// ---------------------------------------------------------------------------
// K3: thread-per-node finalize. Fully coalesced, vectorized.
// ---------------------------------------------------------------------------
__global__ void __launch_bounds__(256) finalize_kernel(
    const float* __restrict__ phase,
    const float* __restrict__ xy,
    const float* __restrict__ xy_dot_old,
    const float* __restrict__ w,
    const float* __restrict__ amp,
    const float* __restrict__ ha,
    float*       __restrict__ out)
{
    int i = blockIdx.x * blockDim.x + threadIdx.x;
    if (i >= N_NODES) return;

    float2 sv = g_sum[i];
    float s, c;
    __sincosf(phase[i], &s, &c);
    float sum_x = fmaf(c, sv.x, -s * sv.y);
    float sum_y = fmaf(s, sv.x,  c * sv.y);

    float2 p  = ((const float2*)xy)[i];
    float2 pd = ((const float2*)xy_dot_old)[i];

    float r2   = fmaf(p.x, p.x, p.y * p.y);
    float a    = ALPHA * (1.0f - r2 * r2);
    float zeta = 1.0f - ha[i] * ((pd.x + EPS_) / (fabsf(pd.x) + EPS_));
    float b    = w[i] / (zeta + EPS_);

    float kx = fmaf(a, p.x, -b * p.y);
    float ky = fmaf(b, p.x,  a * p.y);

    float x_dot = fminf(fmaxf(kx + sum_x, pd.x - DIFF_), pd.x + DIFF_);
    float y_dot = fminf(fmaxf(ky + sum_y, pd.y - DIFF_), pd.y + DIFF_);

    float xn = fmaf(x_dot, DT, p.x);
    float yn = fmaf(y_dot, DT, p.y);
    float ang = fminf(fmaxf(amp[i] * yn, -HARD), HARD);

    out[i] = ang;                                              // angles
    ((float2*)(out + N_NODES))[i]     = make_float2(xn, yn);   // xy_new
    ((float2*)(out + 3 * N_NODES))[i] = p;                     // xy_dot_old_new = xy
}

extern "C" void kernel_launch(void* const* d_in, const int* in_sizes, int n_in,
                              void* d_out, int out_size)
{
    const float* xy         = (const float*)d_in[0];
    const float* xy_dot_old = (const float*)d_in[1];
    const float* phase      = (const float*)d_in[2];
    const float* w          = (const float*)d_in[3];
    const float* amplitudes = (const float*)d_in[4];
    const float* ha         = (const float*)d_in[5];
    const int*   edge_src   = (const int*)d_in[6];
    const int*   edge_dst   = (const int*)d_in[7];
    float* out = (float*)d_out;

    int nb_nodes = (N_NODES + 255) / 256;
    uv_kernel<<<nb_nodes, 256>>>(phase, xy);

    int nb_edges = (N_EDGES + 255) / 256;
    edge_scan_kernel<<<nb_edges, 256>>>(edge_src, edge_dst);

    finalize_kernel<<<nb_nodes, 256>>>(phase, xy, xy_dot_old, w, amplitudes,
                                       ha, out);
}